// round 14
// baseline (speedup 1.0000x reference)
#include <cuda_runtime.h>
#include <cuda_fp16.h>
#include <cstdint>

// ---------------- problem constants ----------------
#define NB    64        // batch
#define SSEG  196       // segments
#define MP_   400       // max pixels per segment
#define ND    768       // embed dim
#define NCH   3         // channels
#define HW    50176     // 224*224
#define KPADH 1216      // K padded (halves), multiple of 64
#define KREAL 1200
#define MTOT  12544     // NB*SSEG
#define NCHUNK 98       // 50176/512
#define NCHP  104       // padded chunk stride (104*4B = 416B, 16B-aligned rows)
#define CPIX  512       // pixels per chunk
#define HCH   7         // chunks per hist block (98 = 7*14)

// GEMM tiling
#define BM 128
#define BN 128
#define BKH 64          // halves per k-chunk (=128 bytes per row)

// ---------------- scratch (device globals; no allocation) ----------------
__device__ __half g_feats[(size_t)MTOT * KPADH];  // ~30.5 MB, A matrix [M, KPADH]
__device__ __half g_Wt[(size_t)ND * KPADH];       // ~1.9 MB, B matrix [N, KPADH]
__device__ int    g_hist[(size_t)MTOT * NCHP];    // [b][s][chunk(padded)] bases
__device__ int    g_cnt[MTOT];                    // per-(b,s) pixel count
__device__ int    g_bins[402];                    // sort bin counts (key = 400 - min(cnt,400))
__device__ int    g_perm[MTOT];                   // row permutation, sorted by cnt desc

// ---------------- kernel 1: hist, 7 chunks/block, 4 px/thread int4 (+ zero bins) ----------------
__global__ void __launch_bounds__(HCH * 128)
hist_kernel(const int* __restrict__ seg) {
    __shared__ int h[HCH][SSEG];
    const int b = blockIdx.y, cg = blockIdx.x;   // chunk group (14 per batch)
    const int t = threadIdx.x;                   // 896 threads
    const int sub = t >> 7;                      // chunk within group (0..6)
    const int st = t & 127;                      // thread within chunk
    if (b == 0 && cg == 0 && t < 402) g_bins[t] = 0;
    for (int i = t; i < HCH * SSEG; i += HCH * 128) (&h[0][0])[i] = 0;
    __syncthreads();
    const int chunk = cg * HCH + sub;
    const int4 s4 = *reinterpret_cast<const int4*>(seg + (size_t)b * HW + chunk * CPIX + st * 4);
    atomicAdd(&h[sub][s4.x], 1);
    atomicAdd(&h[sub][s4.y], 1);
    atomicAdd(&h[sub][s4.z], 1);
    atomicAdd(&h[sub][s4.w], 1);
    __syncthreads();
    // write h[sub][s] -> g_hist[(b*SSEG+s)*NCHP + cg*7 + sub] (7-int runs per s)
    int* gout = g_hist + (size_t)b * SSEG * NCHP + cg * HCH;
    for (int i = t; i < HCH * SSEG; i += HCH * 128) {
        const int s = i / HCH, sb = i - s * HCH;
        gout[(size_t)s * NCHP + sb] = h[sb][s];
    }
}

// ---------------- kernel 2: contiguous scan per (b,s); counts; sort-bin hist ----------------
__global__ void scan_kernel() {
    const int idx = blockIdx.x * blockDim.x + threadIdx.x;
    if (idx >= MTOT) return;
    int* row = g_hist + (size_t)idx * NCHP;      // 98 contiguous ints
    int run = 0;
#pragma unroll
    for (int c = 0; c < NCHUNK; c++) {
        const int v = row[c];
        row[c] = run;
        run += v;
    }
    g_cnt[idx] = run;
    const int cc = run < MP_ ? run : MP_;
    atomicAdd(&g_bins[MP_ - cc], 1);             // bin counts for the row sort
}

// ---------------- kernel 3: fused sort (warp scan of bins + smem-cursor placement) ----------------
__global__ void sort_kernel() {          // 1 block, 1024 threads (runs in scatter's shadow)
    __shared__ int scur[402];            // bin cursors (start = exclusive base)
    const int t = threadIdx.x;
    if (t < 32) {
        const int l = t;
        int loc[13];
        int sum = 0;
#pragma unroll
        for (int i = 0; i < 13; i++) {
            const int bin = l * 13 + i;
            const int v = (bin < 402) ? g_bins[bin] : 0;
            loc[i] = sum;
            sum += v;
        }
        int inc = sum;
#pragma unroll
        for (int off = 1; off < 32; off <<= 1) {
            const int n = __shfl_up_sync(0xffffffffu, inc, off);
            if (l >= off) inc += n;
        }
        const int excl = inc - sum;
#pragma unroll
        for (int i = 0; i < 13; i++) {
            const int bin = l * 13 + i;
            if (bin < 402) scur[bin] = excl + loc[i];
        }
    }
    __syncthreads();
    for (int idx = t; idx < MTOT; idx += 1024) {
        int c = g_cnt[idx];
        if (c > MP_) c = MP_;
        const int pos = atomicAdd(&scur[MP_ - c], 1);
        g_perm[pos] = idx;
    }
}

// ---------------- kernel 4: W -> Wt [N][KPADH] (fp16), k = rank*3 + c, smem tiled ----------------
__global__ void transpose_kernel(const float* __restrict__ Wsrc) {
    __shared__ float tile[32][33];
    const int k0 = blockIdx.x * 32;      // K tile (0..KPADH)
    const int n0 = blockIdx.y * 32;      // N tile
    const int tx = threadIdx.x, ty = threadIdx.y;   // 32 x 8
#pragma unroll
    for (int q = 0; q < 4; q++) {
        const int kk = k0 + ty + q * 8;
        float v = 0.f;
        if (kk < KREAL) {
            const int r = kk / 3, c = kk - 3 * r;   // kk = r*3 + c
            v = Wsrc[(size_t)(c * MP_ + r) * ND + n0 + tx];
        }
        tile[ty + q * 8][tx] = v;
    }
    __syncthreads();
#pragma unroll
    for (int q = 0; q < 4; q++) {
        const int n = n0 + ty + q * 8;
        g_Wt[(size_t)n * KPADH + k0 + tx] = __float2half_rn(tile[tx][ty + q * 8]);
    }
}

// ---------------- kernel 5: stable scatter (smem hist-row preload, early loads) ----------------
__global__ void scatter_kernel(const float* __restrict__ img, const int* __restrict__ seg) {
    __shared__ __align__(16) int wh[16][SSEG];   // per-warp histograms
    __shared__ int hrow[SSEG];                   // this chunk's global bases
    const int b = blockIdx.y, chunk = blockIdx.x;
    const int t = threadIdx.x;
    const int w = t >> 5, l = t & 31;

    // early loads: all global reads issued before the histogram/barrier phase
    const int p = chunk * CPIX + t;
    const int s = seg[(size_t)b * HW + p];
    const float v0 = img[((size_t)(b * NCH + 0)) * HW + p];
    const float v1 = img[((size_t)(b * NCH + 1)) * HW + p];
    const float v2 = img[((size_t)(b * NCH + 2)) * HW + p];
    if (t < SSEG) hrow[t] = g_hist[((size_t)(b * SSEG + t)) * NCHP + chunk];

    // vectorized zero of per-warp histograms (16*196 ints = 784 int4)
    int4* whv = reinterpret_cast<int4*>(&wh[0][0]);
    const int4 z4 = make_int4(0, 0, 0, 0);
    for (int i = t; i < (16 * SSEG) / 4; i += CPIX) whv[i] = z4;
    __syncthreads();

    // stable intra-warp rank (lane order == pixel order)
    const unsigned mask = __match_any_sync(0xffffffffu, s);
    const int lt = __popc(mask & ((1u << l) - 1u));
    const int leader = __ffs(mask) - 1;
    if (l == leader) atomicAdd(&wh[w][s], __popc(mask));
    __syncthreads();

    // predicated prefix over lower warps (independent LDS)
    int pre = 0;
#pragma unroll
    for (int ww = 0; ww < 15; ww++) {
        const int v = wh[ww][s];
        pre += (ww < w) ? v : 0;
    }

    const int rank = hrow[s] + pre + lt;
    if (rank < MP_) {
        const __half h0 = __float2half_rn(v0);
        const __half h1 = __float2half_rn(v1);
        const __half h2 = __float2half_rn(v2);
        __half* dst = g_feats + ((size_t)(b * SSEG + s)) * KPADH + rank * 3;
        if (rank & 1) {
            dst[0] = h0;
            *reinterpret_cast<__half2*>(dst + 1) = __halves2half2(h1, h2);
        } else {
            *reinterpret_cast<__half2*>(dst) = __halves2half2(h0, h1);
            dst[2] = h2;
        }
    }
}

// ---------------- kernel 6: fp16 mma.sync GEMM, perm rows, per-tile dynamic K ----------------
__device__ __forceinline__ void mma_fp16(float* d, const uint32_t* a, uint32_t b0, uint32_t b1) {
    asm volatile(
        "mma.sync.aligned.m16n8k16.row.col.f32.f16.f16.f32 "
        "{%0,%1,%2,%3}, {%4,%5,%6,%7}, {%8,%9}, {%0,%1,%2,%3};"
        : "+f"(d[0]), "+f"(d[1]), "+f"(d[2]), "+f"(d[3])
        : "r"(a[0]), "r"(a[1]), "r"(a[2]), "r"(a[3]), "r"(b0), "r"(b1));
}

__device__ __forceinline__ void ldsm4(uint32_t& r0, uint32_t& r1, uint32_t& r2, uint32_t& r3,
                                      uint32_t addr) {
    asm volatile("ldmatrix.sync.aligned.m8n8.x4.shared.b16 {%0,%1,%2,%3}, [%4];"
                 : "=r"(r0), "=r"(r1), "=r"(r2), "=r"(r3) : "r"(addr));
}

__device__ __forceinline__ void cp_async16(uint32_t sa, const void* gptr) {
    asm volatile("cp.async.cg.shared.global [%0], [%1], 16;" :: "r"(sa), "l"(gptr));
}
__device__ __forceinline__ void cp_async16z(uint32_t sa, const void* gptr, int src_bytes) {
    asm volatile("cp.async.cg.shared.global [%0], [%1], 16, %2;" :: "r"(sa), "l"(gptr), "r"(src_bytes));
}

// dynamic smem: [buf0: A 16KB | B 16KB][buf1: A 16KB | B 16KB] = 64KB
#define GEMM_SMEM 65536

__global__ void __launch_bounds__(256)
gemm_fp16_kernel(const float* __restrict__ bias, float* __restrict__ out) {
    extern __shared__ __align__(128) char smem[];
    uint32_t sbase;
    asm("{ .reg .u64 t; cvta.to.shared.u64 t, %1; cvt.u32.u64 %0, t; }" : "=r"(sbase) : "l"((void*)smem));

    __shared__ int s_km;

    const int tid = threadIdx.x;
    const int wid = tid >> 5, lane = tid & 31;
    const int warp_m = wid & 3;          // 4 warps over M (32 rows each)
    const int warp_n = wid >> 2;         // 2 warps over N (64 cols each)
    const int m0 = blockIdx.y * BM;
    const int n0 = blockIdx.x * BN;

    if (tid == 0) s_km = BKH;            // at least one chunk

    const __half* Brow = g_Wt + (size_t)n0 * KPADH;

    // loader mapping: row = tid>>3 (+32 per q), 16B granule = tid&7
    const int ldr = tid >> 3;
    const int ldj = tid & 7;

    // permuted row pointers + valid byte counts for A loader
    const __half* aptr[4];
    int avb[4];
#pragma unroll
    for (int q = 0; q < 4; q++) {
        const int pr = g_perm[m0 + ldr + q * 32];
        aptr[q] = g_feats + (size_t)pr * KPADH;
        int c = g_cnt[pr];
        if (c > MP_) c = MP_;
        avb[q] = 6 * c - ldj * 16;       // bytes valid at granule ldj, before k-chunk offset
    }
    // per-tile kmax over the 128 permuted rows
    if (tid < BM) {
        int c = g_cnt[g_perm[m0 + tid]];
        if (c > MP_) c = MP_;
        atomicMax(&s_km, 3 * c);
    }

    float acc[2][8][4];
#pragma unroll
    for (int i = 0; i < 2; i++)
#pragma unroll
        for (int j = 0; j < 8; j++)
#pragma unroll
            for (int v = 0; v < 4; v++) acc[i][j][v] = 0.f;

    auto issue_loads = [&](int buf, int kc) {
        const int kbase = kc * BKH;
        const int kbyte = kc * 128;
        const uint32_t aDst = sbase + (uint32_t)buf * 32768u;
        const uint32_t bDst = aDst + 16384u;
#pragma unroll
        for (int q = 0; q < 4; q++) {
            const int row = ldr + q * 32;
            const uint32_t off = (uint32_t)row * 128u + (uint32_t)((ldj ^ (row & 7)) << 4);
            int av = avb[q] - kbyte;
            av = av < 0 ? 0 : (av > 16 ? 16 : av);
            cp_async16z(aDst + off, aptr[q] + kbase + ldj * 8, av);
            cp_async16(bDst + off, Brow + (size_t)row * KPADH + kbase + ldj * 8);
        }
        asm volatile("cp.async.commit_group;");
    };

    issue_loads(0, 0);
    __syncthreads();                      // publish s_km
    const int nkc = (s_km + BKH - 1) / BKH;

    // ---- ldmatrix per-lane invariants ----
    const int rowA = warp_m * 32 + (lane & 15);
    const uint32_t aRowOff = (uint32_t)rowA * 128u;
    const int aXor = rowA & 7;
    const int aG = lane >> 4;
    int bXor[4];
    uint32_t bRowOff[4];
#pragma unroll
    for (int jp = 0; jp < 4; jp++) {
        const int rowB = warp_n * 64 + jp * 16 + ((lane >> 4) << 3) + (lane & 7);
        bRowOff[jp] = (uint32_t)rowB * 128u;
        bXor[jp] = rowB & 7;
    }
    const int bG = (lane >> 3) & 1;

    for (int kc = 0; kc < nkc; kc++) {
        const int buf = kc & 1;
        if (kc + 1 < nkc) {
            issue_loads(buf ^ 1, kc + 1);
            asm volatile("cp.async.wait_group 1;");
        } else {
            asm volatile("cp.async.wait_group 0;");
        }
        __syncthreads();

        const uint32_t aBuf = sbase + (uint32_t)buf * 32768u;
        const uint32_t bBuf = aBuf + 16384u;
#pragma unroll
        for (int s = 0; s < 4; s++) {        // 4 k16-steps per 64-half chunk
            uint32_t a0[4], a1[4];
            const uint32_t aAddr = aBuf + aRowOff + (uint32_t)(((s * 2 + aG) ^ aXor) << 4);
            ldsm4(a0[0], a0[1], a0[2], a0[3], aAddr);
            ldsm4(a1[0], a1[1], a1[2], a1[3], aAddr + 16 * 128);
#pragma unroll
            for (int jp = 0; jp < 4; jp++) {
                uint32_t b0, b1, b2, b3;
                const uint32_t bAddr = bBuf + bRowOff[jp] + (uint32_t)(((s * 2 + bG) ^ bXor[jp]) << 4);
                ldsm4(b0, b1, b2, b3, bAddr);
                mma_fp16(acc[0][2 * jp],     a0, b0, b1);
                mma_fp16(acc[1][2 * jp],     a1, b0, b1);
                mma_fp16(acc[0][2 * jp + 1], a0, b2, b3);
                mma_fp16(acc[1][2 * jp + 1], a1, b2, b3);
            }
        }
        __syncthreads();
    }

    // epilogue: rows go back to their original positions via perm
    const int lr = lane >> 2, lc = lane & 3;
#pragma unroll
    for (int i = 0; i < 2; i++) {
        const int rowLo = g_perm[m0 + warp_m * 32 + i * 16 + lr];
        const int rowHi = g_perm[m0 + warp_m * 32 + i * 16 + lr + 8];
#pragma unroll
        for (int j = 0; j < 8; j++) {
            const int col = n0 + warp_n * 64 + j * 8 + lc * 2;
            const float2 bv = *reinterpret_cast<const float2*>(bias + col);
            float2 lo, hi;
            lo.x = acc[i][j][0] + bv.x;
            lo.y = acc[i][j][1] + bv.y;
            hi.x = acc[i][j][2] + bv.x;
            hi.y = acc[i][j][3] + bv.y;
            *reinterpret_cast<float2*>(out + (size_t)rowLo * ND + col) = lo;
            *reinterpret_cast<float2*>(out + (size_t)rowHi * ND + col) = hi;
        }
    }
}

// ---------------- launch: fork side stream so sort+transpose hide under scatter ----------------
extern "C" void kernel_launch(void* const* d_in, const int* in_sizes, int n_in,
                              void* d_out, int out_size) {
    (void)in_sizes; (void)n_in; (void)out_size;
    const float* img  = (const float*)d_in[0];
    const int*   seg  = (const int*)d_in[1];
    const float* Wsrc = (const float*)d_in[2];
    const float* bias = (const float*)d_in[3];
    float* out = (float*)d_out;

    cudaFuncSetAttribute(gemm_fp16_kernel, cudaFuncAttributeMaxDynamicSharedMemorySize, GEMM_SMEM);

    cudaStream_t s1;
    cudaStreamCreateWithFlags(&s1, cudaStreamNonBlocking);
    cudaEvent_t eFork, eScan, eJoin;
    cudaEventCreateWithFlags(&eFork, cudaEventDisableTiming);
    cudaEventCreateWithFlags(&eScan, cudaEventDisableTiming);
    cudaEventCreateWithFlags(&eJoin, cudaEventDisableTiming);

    // fork: transpose depends only on Wsrc
    cudaEventRecord(eFork, 0);
    cudaStreamWaitEvent(s1, eFork, 0);
    transpose_kernel<<<dim3(KPADH / 32, ND / 32), dim3(32, 8), 0, s1>>>(Wsrc);

    // main chain
    hist_kernel<<<dim3(NCHUNK / HCH, NB), HCH * 128>>>(seg);
    scan_kernel<<<(MTOT + 255) / 256, 256>>>();
    cudaEventRecord(eScan, 0);
    cudaStreamWaitEvent(s1, eScan, 0);
    sort_kernel<<<1, 1024, 0, s1>>>();       // runs concurrent with scatter

    scatter_kernel<<<dim3(NCHUNK, NB), CPIX>>>(img, seg);

    // join side stream before GEMM
    cudaEventRecord(eJoin, s1);
    cudaStreamWaitEvent(0, eJoin, 0);
    gemm_fp16_kernel<<<dim3(ND / BN, MTOT / BM), 256, GEMM_SMEM>>>(bias, out);

    cudaEventDestroy(eFork);
    cudaEventDestroy(eScan);
    cudaEventDestroy(eJoin);
    cudaStreamDestroy(s1);
}

// round 15
// speedup vs baseline: 1.3072x; 1.3072x over previous
#include <cuda_runtime.h>
#include <cuda_fp16.h>
#include <cstdint>

// ---------------- problem constants ----------------
#define NB    64        // batch
#define SSEG  196       // segments
#define MP_   400       // max pixels per segment
#define ND    768       // embed dim
#define NCH   3         // channels
#define HW    50176     // 224*224
#define KPADH 1216      // K padded (halves), multiple of 64
#define KREAL 1200
#define MTOT  12544     // NB*SSEG
#define NCHUNK 98       // 50176/512
#define CPIX  512       // pixels per chunk
#define HCH   7         // chunks per hist block (98 = 7*14)

// GEMM tiling
#define BM 128
#define BN 128
#define BKH 64          // halves per k-chunk (=128 bytes per row)

// ---------------- scratch (device globals; no allocation) ----------------
__device__ __half g_feats[(size_t)MTOT * KPADH];  // ~30.5 MB, A matrix [M, KPADH]
__device__ __half g_Wt[(size_t)ND * KPADH];       // ~1.9 MB, B matrix [N, KPADH]
__device__ int    g_hist[NB * NCHUNK * SSEG];     // [b][chunk][s] bases (warp-coalesced)
__device__ int    g_cnt[MTOT];                    // per-(b,s) pixel count
__device__ int    g_bins[402];                    // sort bin counts (key = 400 - min(cnt,400))
__device__ int    g_perm[MTOT];                   // row permutation, sorted by cnt desc

// ---------------- kernel 1: hist, 7 chunks/block, 4 px/thread int4 (+ zero bins) ----------------
__global__ void __launch_bounds__(HCH * 128)
hist_kernel(const int* __restrict__ seg) {
    __shared__ int h[HCH][SSEG];
    const int b = blockIdx.y, cg = blockIdx.x;   // chunk group (14 per batch)
    const int t = threadIdx.x;                   // 896 threads
    const int sub = t >> 7;                      // chunk within group (0..6)
    const int st = t & 127;                      // thread within chunk
    if (b == 0 && cg == 0 && t < 402) g_bins[t] = 0;
    for (int i = t; i < HCH * SSEG; i += HCH * 128) (&h[0][0])[i] = 0;
    __syncthreads();
    const int chunk = cg * HCH + sub;
    const int4 s4 = *reinterpret_cast<const int4*>(seg + (size_t)b * HW + chunk * CPIX + st * 4);
    atomicAdd(&h[sub][s4.x], 1);
    atomicAdd(&h[sub][s4.y], 1);
    atomicAdd(&h[sub][s4.z], 1);
    atomicAdd(&h[sub][s4.w], 1);
    __syncthreads();
    int* gout = &g_hist[((size_t)b * NCHUNK + cg * HCH) * SSEG];
    for (int i = t; i < HCH * SSEG; i += HCH * 128) gout[i] = (&h[0][0])[i];
}

// ---------------- kernel 2: scan over chunks per (b,s); counts; sort-bin hist ----------------
__global__ void scan_kernel() {
    const int idx = blockIdx.x * blockDim.x + threadIdx.x;
    if (idx >= NB * SSEG) return;
    const int b = idx / SSEG, s = idx - b * SSEG;
    int run = 0;
    int* base = &g_hist[(size_t)b * NCHUNK * SSEG + s];
#pragma unroll 7
    for (int c = 0; c < NCHUNK; c++) {
        int* ptr = base + (size_t)c * SSEG;
        int v = *ptr;
        *ptr = run;
        run += v;
    }
    g_cnt[idx] = run;
    int cc = run < MP_ ? run : MP_;
    atomicAdd(&g_bins[MP_ - cc], 1);     // bin counts for the row sort
}

// ---------------- kernel 3: fused sort (warp scan of bins + smem-cursor placement) ----------------
__global__ void sort_kernel() {          // 1 block, 1024 threads (runs in scatter's shadow)
    __shared__ int scur[402];            // bin cursors (start = exclusive base)
    const int t = threadIdx.x;
    if (t < 32) {
        const int l = t;
        int loc[13];
        int sum = 0;
#pragma unroll
        for (int i = 0; i < 13; i++) {
            const int bin = l * 13 + i;
            const int v = (bin < 402) ? g_bins[bin] : 0;
            loc[i] = sum;
            sum += v;
        }
        int inc = sum;
#pragma unroll
        for (int off = 1; off < 32; off <<= 1) {
            const int n = __shfl_up_sync(0xffffffffu, inc, off);
            if (l >= off) inc += n;
        }
        const int excl = inc - sum;
#pragma unroll
        for (int i = 0; i < 13; i++) {
            const int bin = l * 13 + i;
            if (bin < 402) scur[bin] = excl + loc[i];
        }
    }
    __syncthreads();
    for (int idx = t; idx < MTOT; idx += 1024) {
        int c = g_cnt[idx];
        if (c > MP_) c = MP_;
        const int pos = atomicAdd(&scur[MP_ - c], 1);
        g_perm[pos] = idx;
    }
}

// ---------------- kernel 4: W -> Wt [N][KPADH] (fp16), k = rank*3 + c, smem tiled ----------------
__global__ void transpose_kernel(const float* __restrict__ Wsrc) {
    __shared__ float tile[32][33];
    const int k0 = blockIdx.x * 32;      // K tile (0..KPADH)
    const int n0 = blockIdx.y * 32;      // N tile
    const int tx = threadIdx.x, ty = threadIdx.y;   // 32 x 8
#pragma unroll
    for (int q = 0; q < 4; q++) {
        const int kk = k0 + ty + q * 8;
        float v = 0.f;
        if (kk < KREAL) {
            const int r = kk / 3, c = kk - 3 * r;   // kk = r*3 + c
            v = Wsrc[(size_t)(c * MP_ + r) * ND + n0 + tx];
        }
        tile[ty + q * 8][tx] = v;
    }
    __syncthreads();
#pragma unroll
    for (int q = 0; q < 4; q++) {
        const int n = n0 + ty + q * 8;
        g_Wt[(size_t)n * KPADH + k0 + tx] = __float2half_rn(tile[tx][ty + q * 8]);
    }
}

// ---------------- kernel 5: stable scatter (smem hist-row preload, early loads) ----------------
__global__ void scatter_kernel(const float* __restrict__ img, const int* __restrict__ seg) {
    __shared__ __align__(16) int wh[16][SSEG];   // per-warp histograms
    __shared__ int hrow[SSEG];                   // this chunk's global bases
    const int b = blockIdx.y, chunk = blockIdx.x;
    const int t = threadIdx.x;
    const int w = t >> 5, l = t & 31;

    // early loads: all global reads issued before the histogram/barrier phase
    const int p = chunk * CPIX + t;
    const int s = seg[(size_t)b * HW + p];
    const float v0 = img[((size_t)(b * NCH + 0)) * HW + p];
    const float v1 = img[((size_t)(b * NCH + 1)) * HW + p];
    const float v2 = img[((size_t)(b * NCH + 2)) * HW + p];
    if (t < SSEG) hrow[t] = g_hist[((size_t)b * NCHUNK + chunk) * SSEG + t];

    // vectorized zero of per-warp histograms (16*196 ints = 784 int4)
    int4* whv = reinterpret_cast<int4*>(&wh[0][0]);
    const int4 z4 = make_int4(0, 0, 0, 0);
    for (int i = t; i < (16 * SSEG) / 4; i += CPIX) whv[i] = z4;
    __syncthreads();

    // stable intra-warp rank (lane order == pixel order)
    const unsigned mask = __match_any_sync(0xffffffffu, s);
    const int lt = __popc(mask & ((1u << l) - 1u));
    const int leader = __ffs(mask) - 1;
    if (l == leader) atomicAdd(&wh[w][s], __popc(mask));
    __syncthreads();

    // predicated prefix over lower warps (independent LDS)
    int pre = 0;
#pragma unroll
    for (int ww = 0; ww < 15; ww++) {
        const int v = wh[ww][s];
        pre += (ww < w) ? v : 0;
    }

    const int rank = hrow[s] + pre + lt;
    if (rank < MP_) {
        const __half h0 = __float2half_rn(v0);
        const __half h1 = __float2half_rn(v1);
        const __half h2 = __float2half_rn(v2);
        __half* dst = g_feats + ((size_t)(b * SSEG + s)) * KPADH + rank * 3;
        if (rank & 1) {
            dst[0] = h0;
            *reinterpret_cast<__half2*>(dst + 1) = __halves2half2(h1, h2);
        } else {
            *reinterpret_cast<__half2*>(dst) = __halves2half2(h0, h1);
            dst[2] = h2;
        }
    }
}

// ---------------- kernel 6: fp16 mma.sync GEMM, perm rows, per-tile dynamic K ----------------
__device__ __forceinline__ void mma_fp16(float* d, const uint32_t* a, uint32_t b0, uint32_t b1) {
    asm volatile(
        "mma.sync.aligned.m16n8k16.row.col.f32.f16.f16.f32 "
        "{%0,%1,%2,%3}, {%4,%5,%6,%7}, {%8,%9}, {%0,%1,%2,%3};"
        : "+f"(d[0]), "+f"(d[1]), "+f"(d[2]), "+f"(d[3])
        : "r"(a[0]), "r"(a[1]), "r"(a[2]), "r"(a[3]), "r"(b0), "r"(b1));
}

__device__ __forceinline__ void ldsm4(uint32_t& r0, uint32_t& r1, uint32_t& r2, uint32_t& r3,
                                      uint32_t addr) {
    asm volatile("ldmatrix.sync.aligned.m8n8.x4.shared.b16 {%0,%1,%2,%3}, [%4];"
                 : "=r"(r0), "=r"(r1), "=r"(r2), "=r"(r3) : "r"(addr));
}

__device__ __forceinline__ void cp_async16(uint32_t sa, const void* gptr) {
    asm volatile("cp.async.cg.shared.global [%0], [%1], 16;" :: "r"(sa), "l"(gptr));
}
__device__ __forceinline__ void cp_async16z(uint32_t sa, const void* gptr, int src_bytes) {
    asm volatile("cp.async.cg.shared.global [%0], [%1], 16, %2;" :: "r"(sa), "l"(gptr), "r"(src_bytes));
}

// dynamic smem: [buf0: A 16KB | B 16KB][buf1: A 16KB | B 16KB] = 64KB
#define GEMM_SMEM 65536

__global__ void __launch_bounds__(256)
gemm_fp16_kernel(const float* __restrict__ bias, float* __restrict__ out) {
    extern __shared__ __align__(128) char smem[];
    uint32_t sbase;
    asm("{ .reg .u64 t; cvta.to.shared.u64 t, %1; cvt.u32.u64 %0, t; }" : "=r"(sbase) : "l"((void*)smem));

    __shared__ int s_km;

    const int tid = threadIdx.x;
    const int wid = tid >> 5, lane = tid & 31;
    const int warp_m = wid & 3;          // 4 warps over M (32 rows each)
    const int warp_n = wid >> 2;         // 2 warps over N (64 cols each)
    const int m0 = blockIdx.y * BM;
    const int n0 = blockIdx.x * BN;

    if (tid == 0) s_km = BKH;            // at least one chunk

    const __half* Brow = g_Wt + (size_t)n0 * KPADH;

    // loader mapping: row = tid>>3 (+32 per q), 16B granule = tid&7
    const int ldr = tid >> 3;
    const int ldj = tid & 7;

    // permuted row pointers + valid byte counts for A loader
    const __half* aptr[4];
    int avb[4];
#pragma unroll
    for (int q = 0; q < 4; q++) {
        const int pr = g_perm[m0 + ldr + q * 32];
        aptr[q] = g_feats + (size_t)pr * KPADH;
        int c = g_cnt[pr];
        if (c > MP_) c = MP_;
        avb[q] = 6 * c - ldj * 16;       // bytes valid at granule ldj, before k-chunk offset
    }
    // per-tile kmax over the 128 permuted rows
    if (tid < BM) {
        int c = g_cnt[g_perm[m0 + tid]];
        if (c > MP_) c = MP_;
        atomicMax(&s_km, 3 * c);
    }

    float acc[2][8][4];
#pragma unroll
    for (int i = 0; i < 2; i++)
#pragma unroll
        for (int j = 0; j < 8; j++)
#pragma unroll
            for (int v = 0; v < 4; v++) acc[i][j][v] = 0.f;

    auto issue_loads = [&](int buf, int kc) {
        const int kbase = kc * BKH;
        const int kbyte = kc * 128;
        const uint32_t aDst = sbase + (uint32_t)buf * 32768u;
        const uint32_t bDst = aDst + 16384u;
#pragma unroll
        for (int q = 0; q < 4; q++) {
            const int row = ldr + q * 32;
            const uint32_t off = (uint32_t)row * 128u + (uint32_t)((ldj ^ (row & 7)) << 4);
            int av = avb[q] - kbyte;
            av = av < 0 ? 0 : (av > 16 ? 16 : av);
            cp_async16z(aDst + off, aptr[q] + kbase + ldj * 8, av);
            cp_async16(bDst + off, Brow + (size_t)row * KPADH + kbase + ldj * 8);
        }
        asm volatile("cp.async.commit_group;");
    };

    issue_loads(0, 0);
    __syncthreads();                      // publish s_km
    const int nkc = (s_km + BKH - 1) / BKH;

    // ---- ldmatrix per-lane invariants ----
    const int rowA = warp_m * 32 + (lane & 15);
    const uint32_t aRowOff = (uint32_t)rowA * 128u;
    const int aXor = rowA & 7;
    const int aG = lane >> 4;
    int bXor[4];
    uint32_t bRowOff[4];
#pragma unroll
    for (int jp = 0; jp < 4; jp++) {
        const int rowB = warp_n * 64 + jp * 16 + ((lane >> 4) << 3) + (lane & 7);
        bRowOff[jp] = (uint32_t)rowB * 128u;
        bXor[jp] = rowB & 7;
    }
    const int bG = (lane >> 3) & 1;

    for (int kc = 0; kc < nkc; kc++) {
        const int buf = kc & 1;
        if (kc + 1 < nkc) {
            issue_loads(buf ^ 1, kc + 1);
            asm volatile("cp.async.wait_group 1;");
        } else {
            asm volatile("cp.async.wait_group 0;");
        }
        __syncthreads();

        const uint32_t aBuf = sbase + (uint32_t)buf * 32768u;
        const uint32_t bBuf = aBuf + 16384u;
#pragma unroll
        for (int s = 0; s < 4; s++) {        // 4 k16-steps per 64-half chunk
            uint32_t a0[4], a1[4];
            const uint32_t aAddr = aBuf + aRowOff + (uint32_t)(((s * 2 + aG) ^ aXor) << 4);
            ldsm4(a0[0], a0[1], a0[2], a0[3], aAddr);
            ldsm4(a1[0], a1[1], a1[2], a1[3], aAddr + 16 * 128);
#pragma unroll
            for (int jp = 0; jp < 4; jp++) {
                uint32_t b0, b1, b2, b3;
                const uint32_t bAddr = bBuf + bRowOff[jp] + (uint32_t)(((s * 2 + bG) ^ bXor[jp]) << 4);
                ldsm4(b0, b1, b2, b3, bAddr);
                mma_fp16(acc[0][2 * jp],     a0, b0, b1);
                mma_fp16(acc[1][2 * jp],     a1, b0, b1);
                mma_fp16(acc[0][2 * jp + 1], a0, b2, b3);
                mma_fp16(acc[1][2 * jp + 1], a1, b2, b3);
            }
        }
        __syncthreads();
    }

    // epilogue: rows go back to their original positions via perm
    const int lr = lane >> 2, lc = lane & 3;
#pragma unroll
    for (int i = 0; i < 2; i++) {
        const int rowLo = g_perm[m0 + warp_m * 32 + i * 16 + lr];
        const int rowHi = g_perm[m0 + warp_m * 32 + i * 16 + lr + 8];
#pragma unroll
        for (int j = 0; j < 8; j++) {
            const int col = n0 + warp_n * 64 + j * 8 + lc * 2;
            const float2 bv = *reinterpret_cast<const float2*>(bias + col);
            float2 lo, hi;
            lo.x = acc[i][j][0] + bv.x;
            lo.y = acc[i][j][1] + bv.y;
            hi.x = acc[i][j][2] + bv.x;
            hi.y = acc[i][j][3] + bv.y;
            *reinterpret_cast<float2*>(out + (size_t)rowLo * ND + col) = lo;
            *reinterpret_cast<float2*>(out + (size_t)rowHi * ND + col) = hi;
        }
    }
}

// ---------------- launch: fork side stream so sort+transpose hide under scatter ----------------
extern "C" void kernel_launch(void* const* d_in, const int* in_sizes, int n_in,
                              void* d_out, int out_size) {
    (void)in_sizes; (void)n_in; (void)out_size;
    const float* img  = (const float*)d_in[0];
    const int*   seg  = (const int*)d_in[1];
    const float* Wsrc = (const float*)d_in[2];
    const float* bias = (const float*)d_in[3];
    float* out = (float*)d_out;

    cudaFuncSetAttribute(gemm_fp16_kernel, cudaFuncAttributeMaxDynamicSharedMemorySize, GEMM_SMEM);

    cudaStream_t s1;
    cudaStreamCreateWithFlags(&s1, cudaStreamNonBlocking);
    cudaEvent_t eFork, eScan, eJoin;
    cudaEventCreateWithFlags(&eFork, cudaEventDisableTiming);
    cudaEventCreateWithFlags(&eScan, cudaEventDisableTiming);
    cudaEventCreateWithFlags(&eJoin, cudaEventDisableTiming);

    // fork: transpose depends only on Wsrc
    cudaEventRecord(eFork, 0);
    cudaStreamWaitEvent(s1, eFork, 0);
    transpose_kernel<<<dim3(KPADH / 32, ND / 32), dim3(32, 8), 0, s1>>>(Wsrc);

    // main chain
    hist_kernel<<<dim3(NCHUNK / HCH, NB), HCH * 128>>>(seg);
    scan_kernel<<<(MTOT + 255) / 256, 256>>>();
    cudaEventRecord(eScan, 0);
    cudaStreamWaitEvent(s1, eScan, 0);
    sort_kernel<<<1, 1024, 0, s1>>>();       // runs concurrent with scatter

    scatter_kernel<<<dim3(NCHUNK, NB), CPIX>>>(img, seg);

    // join side stream before GEMM
    cudaEventRecord(eJoin, s1);
    cudaStreamWaitEvent(0, eJoin, 0);
    gemm_fp16_kernel<<<dim3(ND / BN, MTOT / BM), 256, GEMM_SMEM>>>(bias, out);

    cudaEventDestroy(eFork);
    cudaEventDestroy(eScan);
    cudaEventDestroy(eJoin);
    cudaStreamDestroy(s1);
}

// round 16
// speedup vs baseline: 1.3276x; 1.0156x over previous
#include <cuda_runtime.h>
#include <cuda_fp16.h>
#include <cstdint>

// ---------------- problem constants ----------------
#define NB    64        // batch
#define SSEG  196       // segments
#define MP_   400       // max pixels per segment
#define ND    768       // embed dim
#define NCH   3         // channels
#define HW    50176     // 224*224
#define KPADH 1216      // K padded (halves), multiple of 64
#define KREAL 1200
#define MTOT  12544     // NB*SSEG
#define NCHUNK 98       // 50176/512
#define CPIX  512       // pixels per chunk
#define HCH   7         // chunks per hist block (98 = 7*14)

// GEMM tiling
#define BM 128
#define BN 128
#define BKH 64          // halves per k-chunk (=128 bytes per row)

// ---------------- scratch (device globals; no allocation) ----------------
__device__ __half g_feats[(size_t)MTOT * KPADH];  // ~30.5 MB, A matrix [M, KPADH]
__device__ __half g_Wt[(size_t)ND * KPADH];       // ~1.9 MB, B matrix [N, KPADH]
__device__ int    g_hist[NB * NCHUNK * SSEG];     // [b][chunk][s] bases (warp-coalesced)
__device__ int    g_cnt[MTOT];                    // per-(b,s) pixel count
__device__ int    g_bins[402];                    // sort bin counts (key = 400 - min(cnt,400))
__device__ int    g_perm[MTOT];                   // row permutation, sorted by cnt desc

// ---------------- kernel 1: hist, 7 chunks/block, 4 px/thread int4 (+ zero bins) ----------------
__global__ void __launch_bounds__(HCH * 128)
hist_kernel(const int* __restrict__ seg) {
    __shared__ int h[HCH][SSEG];
    const int b = blockIdx.y, cg = blockIdx.x;   // chunk group (14 per batch)
    const int t = threadIdx.x;                   // 896 threads
    const int sub = t >> 7;                      // chunk within group (0..6)
    const int st = t & 127;                      // thread within chunk
    if (b == 0 && cg == 0 && t < 402) g_bins[t] = 0;
    for (int i = t; i < HCH * SSEG; i += HCH * 128) (&h[0][0])[i] = 0;
    __syncthreads();
    const int chunk = cg * HCH + sub;
    const int4 s4 = *reinterpret_cast<const int4*>(seg + (size_t)b * HW + chunk * CPIX + st * 4);
    atomicAdd(&h[sub][s4.x], 1);
    atomicAdd(&h[sub][s4.y], 1);
    atomicAdd(&h[sub][s4.z], 1);
    atomicAdd(&h[sub][s4.w], 1);
    __syncthreads();
    int* gout = &g_hist[((size_t)b * NCHUNK + cg * HCH) * SSEG];
    for (int i = t; i < HCH * SSEG; i += HCH * 128) gout[i] = (&h[0][0])[i];
}

// ---------------- kernel 2: scan over chunks per (b,s); counts; sort-bin hist ----------------
__global__ void scan_kernel() {
    const int idx = blockIdx.x * blockDim.x + threadIdx.x;
    if (idx >= NB * SSEG) return;
    const int b = idx / SSEG, s = idx - b * SSEG;
    int run = 0;
    int* base = &g_hist[(size_t)b * NCHUNK * SSEG + s];
#pragma unroll 7
    for (int c = 0; c < NCHUNK; c++) {
        int* ptr = base + (size_t)c * SSEG;
        int v = *ptr;
        *ptr = run;
        run += v;
    }
    g_cnt[idx] = run;
    int cc = run < MP_ ? run : MP_;
    atomicAdd(&g_bins[MP_ - cc], 1);     // bin counts for the row sort
}

// ---------------- kernel 3: fused sort (warp scan of bins + smem-cursor placement) ----------------
__global__ void sort_kernel() {          // 1 block, 1024 threads (runs in scatter's shadow)
    __shared__ int scur[402];            // bin cursors (start = exclusive base)
    const int t = threadIdx.x;
    if (t < 32) {
        const int l = t;
        int loc[13];
        int sum = 0;
#pragma unroll
        for (int i = 0; i < 13; i++) {
            const int bin = l * 13 + i;
            const int v = (bin < 402) ? g_bins[bin] : 0;
            loc[i] = sum;
            sum += v;
        }
        int inc = sum;
#pragma unroll
        for (int off = 1; off < 32; off <<= 1) {
            const int n = __shfl_up_sync(0xffffffffu, inc, off);
            if (l >= off) inc += n;
        }
        const int excl = inc - sum;
#pragma unroll
        for (int i = 0; i < 13; i++) {
            const int bin = l * 13 + i;
            if (bin < 402) scur[bin] = excl + loc[i];
        }
    }
    __syncthreads();
    for (int idx = t; idx < MTOT; idx += 1024) {
        int c = g_cnt[idx];
        if (c > MP_) c = MP_;
        const int pos = atomicAdd(&scur[MP_ - c], 1);
        g_perm[pos] = idx;
    }
}

// ---------------- kernel 4: W -> Wt [N][KPADH] (fp16), k = rank*3 + c, smem tiled ----------------
__global__ void transpose_kernel(const float* __restrict__ Wsrc) {
    __shared__ float tile[32][33];
    const int k0 = blockIdx.x * 32;      // K tile (0..KPADH)
    const int n0 = blockIdx.y * 32;      // N tile
    const int tx = threadIdx.x, ty = threadIdx.y;   // 32 x 8
#pragma unroll
    for (int q = 0; q < 4; q++) {
        const int kk = k0 + ty + q * 8;
        float v = 0.f;
        if (kk < KREAL) {
            const int r = kk / 3, c = kk - 3 * r;   // kk = r*3 + c
            v = Wsrc[(size_t)(c * MP_ + r) * ND + n0 + tx];
        }
        tile[ty + q * 8][tx] = v;
    }
    __syncthreads();
#pragma unroll
    for (int q = 0; q < 4; q++) {
        const int n = n0 + ty + q * 8;
        g_Wt[(size_t)n * KPADH + k0 + tx] = __float2half_rn(tile[tx][ty + q * 8]);
    }
}

// ---------------- kernel 5: stable scatter (smem hist-row preload, early loads) ----------------
__global__ void scatter_kernel(const float* __restrict__ img, const int* __restrict__ seg) {
    __shared__ __align__(16) int wh[16][SSEG];   // per-warp histograms
    __shared__ int hrow[SSEG];                   // this chunk's global bases
    const int b = blockIdx.y, chunk = blockIdx.x;
    const int t = threadIdx.x;
    const int w = t >> 5, l = t & 31;

    // early loads: all global reads issued before the histogram/barrier phase
    const int p = chunk * CPIX + t;
    const int s = seg[(size_t)b * HW + p];
    const float v0 = img[((size_t)(b * NCH + 0)) * HW + p];
    const float v1 = img[((size_t)(b * NCH + 1)) * HW + p];
    const float v2 = img[((size_t)(b * NCH + 2)) * HW + p];
    if (t < SSEG) hrow[t] = g_hist[((size_t)b * NCHUNK + chunk) * SSEG + t];

    // vectorized zero of per-warp histograms (16*196 ints = 784 int4)
    int4* whv = reinterpret_cast<int4*>(&wh[0][0]);
    const int4 z4 = make_int4(0, 0, 0, 0);
    for (int i = t; i < (16 * SSEG) / 4; i += CPIX) whv[i] = z4;
    __syncthreads();

    // stable intra-warp rank (lane order == pixel order)
    const unsigned mask = __match_any_sync(0xffffffffu, s);
    const int lt = __popc(mask & ((1u << l) - 1u));
    const int leader = __ffs(mask) - 1;
    if (l == leader) atomicAdd(&wh[w][s], __popc(mask));
    __syncthreads();

    // predicated prefix over lower warps (independent LDS)
    int pre = 0;
#pragma unroll
    for (int ww = 0; ww < 15; ww++) {
        const int v = wh[ww][s];
        pre += (ww < w) ? v : 0;
    }

    const int rank = hrow[s] + pre + lt;
    if (rank < MP_) {
        const __half h0 = __float2half_rn(v0);
        const __half h1 = __float2half_rn(v1);
        const __half h2 = __float2half_rn(v2);
        __half* dst = g_feats + ((size_t)(b * SSEG + s)) * KPADH + rank * 3;
        if (rank & 1) {
            dst[0] = h0;
            *reinterpret_cast<__half2*>(dst + 1) = __halves2half2(h1, h2);
        } else {
            *reinterpret_cast<__half2*>(dst) = __halves2half2(h0, h1);
            dst[2] = h2;
        }
    }
}

// ---------------- kernel 6: fp16 mma.sync GEMM, perm rows, per-tile dynamic K ----------------
__device__ __forceinline__ void mma_fp16(float* d, const uint32_t* a, uint32_t b0, uint32_t b1) {
    asm volatile(
        "mma.sync.aligned.m16n8k16.row.col.f32.f16.f16.f32 "
        "{%0,%1,%2,%3}, {%4,%5,%6,%7}, {%8,%9}, {%0,%1,%2,%3};"
        : "+f"(d[0]), "+f"(d[1]), "+f"(d[2]), "+f"(d[3])
        : "r"(a[0]), "r"(a[1]), "r"(a[2]), "r"(a[3]), "r"(b0), "r"(b1));
}

__device__ __forceinline__ void ldsm4(uint32_t& r0, uint32_t& r1, uint32_t& r2, uint32_t& r3,
                                      uint32_t addr) {
    asm volatile("ldmatrix.sync.aligned.m8n8.x4.shared.b16 {%0,%1,%2,%3}, [%4];"
                 : "=r"(r0), "=r"(r1), "=r"(r2), "=r"(r3) : "r"(addr));
}

__device__ __forceinline__ void cp_async16(uint32_t sa, const void* gptr) {
    asm volatile("cp.async.cg.shared.global [%0], [%1], 16;" :: "r"(sa), "l"(gptr));
}
__device__ __forceinline__ void cp_async16z(uint32_t sa, const void* gptr, int src_bytes) {
    asm volatile("cp.async.cg.shared.global [%0], [%1], 16, %2;" :: "r"(sa), "l"(gptr), "r"(src_bytes));
}

// dynamic smem: [buf0: A 16KB | B 16KB][buf1: A 16KB | B 16KB] = 64KB per CTA
#define GEMM_SMEM 65536

__global__ void __launch_bounds__(256, 2)    // 2 CTAs/SM: fill sync/load bubbles
gemm_fp16_kernel(const float* __restrict__ bias, float* __restrict__ out) {
    extern __shared__ __align__(128) char smem[];
    uint32_t sbase;
    asm("{ .reg .u64 t; cvta.to.shared.u64 t, %1; cvt.u32.u64 %0, t; }" : "=r"(sbase) : "l"((void*)smem));

    __shared__ int s_km;

    const int tid = threadIdx.x;
    const int wid = tid >> 5, lane = tid & 31;
    const int warp_m = wid & 3;          // 4 warps over M (32 rows each)
    const int warp_n = wid >> 2;         // 2 warps over N (64 cols each)
    const int m0 = blockIdx.y * BM;
    const int n0 = blockIdx.x * BN;

    if (tid == 0) s_km = BKH;            // at least one chunk

    const __half* Brow = g_Wt + (size_t)n0 * KPADH;

    // loader mapping: row = tid>>3 (+32 per q), 16B granule = tid&7
    const int ldr = tid >> 3;
    const int ldj = tid & 7;

    // permuted row pointers + valid byte counts for A loader
    const __half* aptr[4];
    int avb[4];
#pragma unroll
    for (int q = 0; q < 4; q++) {
        const int pr = g_perm[m0 + ldr + q * 32];
        aptr[q] = g_feats + (size_t)pr * KPADH;
        int c = g_cnt[pr];
        if (c > MP_) c = MP_;
        avb[q] = 6 * c - ldj * 16;       // bytes valid at granule ldj, before k-chunk offset
    }
    // per-tile kmax over the 128 permuted rows
    if (tid < BM) {
        int c = g_cnt[g_perm[m0 + tid]];
        if (c > MP_) c = MP_;
        atomicMax(&s_km, 3 * c);
    }

    float acc[2][8][4];
#pragma unroll
    for (int i = 0; i < 2; i++)
#pragma unroll
        for (int j = 0; j < 8; j++)
#pragma unroll
            for (int v = 0; v < 4; v++) acc[i][j][v] = 0.f;

    auto issue_loads = [&](int buf, int kc) {
        const int kbase = kc * BKH;
        const int kbyte = kc * 128;
        const uint32_t aDst = sbase + (uint32_t)buf * 32768u;
        const uint32_t bDst = aDst + 16384u;
#pragma unroll
        for (int q = 0; q < 4; q++) {
            const int row = ldr + q * 32;
            const uint32_t off = (uint32_t)row * 128u + (uint32_t)((ldj ^ (row & 7)) << 4);
            int av = avb[q] - kbyte;
            av = av < 0 ? 0 : (av > 16 ? 16 : av);
            cp_async16z(aDst + off, aptr[q] + kbase + ldj * 8, av);
            cp_async16(bDst + off, Brow + (size_t)row * KPADH + kbase + ldj * 8);
        }
        asm volatile("cp.async.commit_group;");
    };

    issue_loads(0, 0);
    __syncthreads();                      // publish s_km
    const int nkc = (s_km + BKH - 1) / BKH;

    // ---- ldmatrix per-lane invariants ----
    const int rowA = warp_m * 32 + (lane & 15);
    const uint32_t aRowOff = (uint32_t)rowA * 128u;
    const int aXor = rowA & 7;
    const int aG = lane >> 4;
    int bXor[4];
    uint32_t bRowOff[4];
#pragma unroll
    for (int jp = 0; jp < 4; jp++) {
        const int rowB = warp_n * 64 + jp * 16 + ((lane >> 4) << 3) + (lane & 7);
        bRowOff[jp] = (uint32_t)rowB * 128u;
        bXor[jp] = rowB & 7;
    }
    const int bG = (lane >> 3) & 1;

    for (int kc = 0; kc < nkc; kc++) {
        const int buf = kc & 1;
        if (kc + 1 < nkc) {
            issue_loads(buf ^ 1, kc + 1);
            asm volatile("cp.async.wait_group 1;");
        } else {
            asm volatile("cp.async.wait_group 0;");
        }
        __syncthreads();

        const uint32_t aBuf = sbase + (uint32_t)buf * 32768u;
        const uint32_t bBuf = aBuf + 16384u;
#pragma unroll
        for (int s = 0; s < 4; s++) {        // 4 k16-steps per 64-half chunk
            uint32_t a0[4], a1[4];
            const uint32_t aAddr = aBuf + aRowOff + (uint32_t)(((s * 2 + aG) ^ aXor) << 4);
            ldsm4(a0[0], a0[1], a0[2], a0[3], aAddr);
            ldsm4(a1[0], a1[1], a1[2], a1[3], aAddr + 16 * 128);
#pragma unroll
            for (int jp = 0; jp < 4; jp++) {
                uint32_t b0, b1, b2, b3;
                const uint32_t bAddr = bBuf + bRowOff[jp] + (uint32_t)(((s * 2 + bG) ^ bXor[jp]) << 4);
                ldsm4(b0, b1, b2, b3, bAddr);
                mma_fp16(acc[0][2 * jp],     a0, b0, b1);
                mma_fp16(acc[1][2 * jp],     a1, b0, b1);
                mma_fp16(acc[0][2 * jp + 1], a0, b2, b3);
                mma_fp16(acc[1][2 * jp + 1], a1, b2, b3);
            }
        }
        __syncthreads();
    }

    // epilogue: rows go back to their original positions via perm
    const int lr = lane >> 2, lc = lane & 3;
#pragma unroll
    for (int i = 0; i < 2; i++) {
        const int rowLo = g_perm[m0 + warp_m * 32 + i * 16 + lr];
        const int rowHi = g_perm[m0 + warp_m * 32 + i * 16 + lr + 8];
#pragma unroll
        for (int j = 0; j < 8; j++) {
            const int col = n0 + warp_n * 64 + j * 8 + lc * 2;
            const float2 bv = *reinterpret_cast<const float2*>(bias + col);
            float2 lo, hi;
            lo.x = acc[i][j][0] + bv.x;
            lo.y = acc[i][j][1] + bv.y;
            hi.x = acc[i][j][2] + bv.x;
            hi.y = acc[i][j][3] + bv.y;
            *reinterpret_cast<float2*>(out + (size_t)rowLo * ND + col) = lo;
            *reinterpret_cast<float2*>(out + (size_t)rowHi * ND + col) = hi;
        }
    }
}

// ---------------- launch: fork side stream so sort+transpose hide under scatter ----------------
extern "C" void kernel_launch(void* const* d_in, const int* in_sizes, int n_in,
                              void* d_out, int out_size) {
    (void)in_sizes; (void)n_in; (void)out_size;
    const float* img  = (const float*)d_in[0];
    const int*   seg  = (const int*)d_in[1];
    const float* Wsrc = (const float*)d_in[2];
    const float* bias = (const float*)d_in[3];
    float* out = (float*)d_out;

    cudaFuncSetAttribute(gemm_fp16_kernel, cudaFuncAttributeMaxDynamicSharedMemorySize, GEMM_SMEM);

    cudaStream_t s1;
    cudaStreamCreateWithFlags(&s1, cudaStreamNonBlocking);
    cudaEvent_t eFork, eScan, eJoin;
    cudaEventCreateWithFlags(&eFork, cudaEventDisableTiming);
    cudaEventCreateWithFlags(&eScan, cudaEventDisableTiming);
    cudaEventCreateWithFlags(&eJoin, cudaEventDisableTiming);

    // fork: transpose depends only on Wsrc
    cudaEventRecord(eFork, 0);
    cudaStreamWaitEvent(s1, eFork, 0);
    transpose_kernel<<<dim3(KPADH / 32, ND / 32), dim3(32, 8), 0, s1>>>(Wsrc);

    // main chain
    hist_kernel<<<dim3(NCHUNK / HCH, NB), HCH * 128>>>(seg);
    scan_kernel<<<(MTOT + 255) / 256, 256>>>();
    cudaEventRecord(eScan, 0);
    cudaStreamWaitEvent(s1, eScan, 0);
    sort_kernel<<<1, 1024, 0, s1>>>();       // runs concurrent with scatter

    scatter_kernel<<<dim3(NCHUNK, NB), CPIX>>>(img, seg);

    // join side stream before GEMM
    cudaEventRecord(eJoin, s1);
    cudaStreamWaitEvent(0, eJoin, 0);
    gemm_fp16_kernel<<<dim3(ND / BN, MTOT / BM), 256, GEMM_SMEM>>>(bias, out);

    cudaEventDestroy(eFork);
    cudaEventDestroy(eScan);
    cudaEventDestroy(eJoin);
    cudaStreamDestroy(s1);
}